// round 2
// baseline (speedup 1.0000x reference)
#include <cuda_runtime.h>
#include <stdint.h>

// Problem constants (sized for this dataset; guarded at runtime)
#define MAX_NODES 500000
// Node-major scratch: [N, 128] floats — pos channels 0..63, neg channels 64..127
__device__ __align__(16) float g_scratch[(size_t)MAX_NODES * 128];

// ---------------------------------------------------------------------------
// Kernel 1: transpose phi_k_pos/neg [64, N] (channel-major) -> scratch [N,128]
// Tile: 32 nodes x 64 channels per block, 256 threads.
// smem layout: s_pos[c*33 + nl], s_neg[c*33 + nl] (stride 33 => conflict-free
// on both the store phase (nl = lane) and the load phase (c = lane)).
// ---------------------------------------------------------------------------
__global__ __launch_bounds__(256) void transpose_phi_kernel(
    const float* __restrict__ pos,
    const float* __restrict__ neg,
    float* __restrict__ scratch,
    int N)
{
    __shared__ float s_pos[64 * 33];
    __shared__ float s_neg[64 * 33];

    const int n0  = blockIdx.x * 32;
    const int tid = threadIdx.x;

    // Load: 64 channels x 32 nodes, coalesced 128B per warp-phase
    #pragma unroll
    for (int it = 0; it < 8; ++it) {
        int idx = it * 256 + tid;      // 0..2047
        int c   = idx >> 5;            // channel 0..63
        int nl  = idx & 31;            // node-in-tile
        int n   = n0 + nl;
        float vp = 0.f, vn = 0.f;
        if (n < N) {
            vp = pos[(size_t)c * N + n];
            vn = neg[(size_t)c * N + n];
        }
        s_pos[c * 33 + nl] = vp;
        s_neg[c * 33 + nl] = vn;
    }
    __syncthreads();

    // Store: 32 nodes x 128 channels, coalesced 128B per warp-phase
    #pragma unroll
    for (int it = 0; it < 16; ++it) {
        int idx = it * 256 + tid;      // 0..4095
        int nl  = idx >> 7;            // node-in-tile
        int k   = idx & 127;           // output channel 0..127
        int n   = n0 + nl;
        if (n < N) {
            float v = (k < 64) ? s_pos[k * 33 + nl] : s_neg[(k - 64) * 33 + nl];
            scratch[(size_t)n * 128 + k] = v;
        }
    }
}

// ---------------------------------------------------------------------------
// Kernel 2: one thread per (query, head).
//   j = k_indices[i]
//   out[i*8+h]           = dot8(q_phi[i,h,:], scratch[j, h*8 : h*8+8])    / max(deg_pos[j,h],1)
//   out[Nq*8 + i*8 + h]  = dot8(q_phi[i,h,:], scratch[j, 64+h*8 : +8])    / max(deg_neg[j,h],1)
// ---------------------------------------------------------------------------
__global__ __launch_bounds__(256) void iskde_gather_kernel(
    const float* __restrict__ q_phi,    // [Nq, 64]
    const float* __restrict__ scratch,  // [N, 128]
    const float* __restrict__ deg_pos,  // [N, 8]
    const float* __restrict__ deg_neg,  // [N, 8]
    const int*   __restrict__ k_idx,    // [Nq]
    float* __restrict__ out,            // [2 * Nq * 8]
    int nq)
{
    int t = blockIdx.x * blockDim.x + threadIdx.x;   // (query, head) id
    int total = nq * 8;
    if (t >= total) return;

    int i = t >> 3;
    int h = t & 7;
    int j = __ldg(&k_idx[i]);

    // q_phi[i, h, :] : 8 contiguous floats at offset t*8
    const float4* qp = reinterpret_cast<const float4*>(q_phi + (size_t)t * 8);
    float4 q0 = qp[0];
    float4 q1 = qp[1];

    // scratch[j, h*8 .. ] (pos) and scratch[j, 64 + h*8 ..] (neg)
    const float4* pk = reinterpret_cast<const float4*>(scratch + (size_t)j * 128 + h * 8);
    float4 p0 = pk[0];
    float4 p1 = pk[1];
    float4 m0 = pk[16];   // +64 floats = +16 float4
    float4 m1 = pk[17];

    float dp = q0.x * p0.x + q0.y * p0.y + q0.z * p0.z + q0.w * p0.w
             + q1.x * p1.x + q1.y * p1.y + q1.z * p1.z + q1.w * p1.w;
    float dn = q0.x * m0.x + q0.y * m0.y + q0.z * m0.z + q0.w * m0.w
             + q1.x * m1.x + q1.y * m1.y + q1.z * m1.z + q1.w * m1.w;

    float denp = fmaxf(__ldg(&deg_pos[(size_t)j * 8 + h]), 1.0f);
    float denn = fmaxf(__ldg(&deg_neg[(size_t)j * 8 + h]), 1.0f);

    out[t]                    = dp / denp;
    out[(size_t)total + t]    = dn / denn;
}

// ---------------------------------------------------------------------------
// Launch: inputs in metadata order:
//   0: q_phi   [Nq, 8, 8] f32
//   1: phi_k_pos [8, 8, N] f32
//   2: phi_k_neg [8, 8, N] f32
//   3: deg_pos [N, 8] f32
//   4: deg_neg [N, 8] f32
//   5: k_indices [Nq] i32
// Output: concat(num_pos/den_pos [Nq,8], num_neg/den_neg [Nq,8]) f32
// ---------------------------------------------------------------------------
extern "C" void kernel_launch(void* const* d_in, const int* in_sizes, int n_in,
                              void* d_out, int out_size)
{
    const float* q_phi   = (const float*)d_in[0];
    const float* phi_pos = (const float*)d_in[1];
    const float* phi_neg = (const float*)d_in[2];
    const float* deg_pos = (const float*)d_in[3];
    const float* deg_neg = (const float*)d_in[4];
    const int*   k_idx   = (const int*)d_in[5];

    int nq = in_sizes[0] / 64;   // q_phi elements / (H*MH)
    int N  = in_sizes[1] / 64;   // phi_k elements / (H*MH)
    if (N > MAX_NODES) N = MAX_NODES;  // scratch capacity guard

    float* scratch;
    cudaGetSymbolAddress((void**)&scratch, g_scratch);

    // Kernel 1: transpose into node-major scratch
    int tblocks = (N + 31) / 32;
    transpose_phi_kernel<<<tblocks, 256>>>(phi_pos, phi_neg, scratch, N);

    // Kernel 2: gather + dot + normalize
    int total  = nq * 8;
    int gblocks = (total + 255) / 256;
    iskde_gather_kernel<<<gblocks, 256>>>(q_phi, scratch, deg_pos, deg_neg,
                                          k_idx, (float*)d_out, nq);
}

// round 4
// speedup vs baseline: 1.3019x; 1.3019x over previous
#include <cuda_runtime.h>
#include <cuda_fp16.h>
#include <stdint.h>

#define MAX_NODES 500000
#define ROW_F 80   // floats per packed row: 64 (=128 halves of phi) + 16 f32 inv_deg
// Packed node-major scratch: per node 320 B:
//   bytes [0,128)   : 64 halves = pos channels 0..63
//   bytes [128,256) : 64 halves = neg channels 0..63
//   bytes [256,288) : 8 f32 = 1/max(deg_pos,1)
//   bytes [288,320) : 8 f32 = 1/max(deg_neg,1)
__device__ __align__(16) float g_scratch[(size_t)MAX_NODES * ROW_F];

// ---------------------------------------------------------------------------
// Kernel 1: transpose+pack. Tile = 32 nodes, block = 256 threads.
// smem stride 33 keeps load phase conflict-free and store phase <=2-way.
// ---------------------------------------------------------------------------
__global__ __launch_bounds__(256) void pack_kernel(
    const float* __restrict__ pos,
    const float* __restrict__ neg,
    const float* __restrict__ deg_pos,
    const float* __restrict__ deg_neg,
    float* __restrict__ scratch,
    int N)
{
    __shared__ float s_pos[64 * 33];
    __shared__ float s_neg[64 * 33];

    const int n0  = blockIdx.x * 32;
    const int tid = threadIdx.x;

    // ---- Load phase: float4 over nodes, 64 channels x 8 float4 per array ----
    #pragma unroll
    for (int it = 0; it < 2; ++it) {
        int idx = it * 256 + tid;          // 0..511
        int c   = idx >> 3;                // channel 0..63
        int n4  = idx & 7;                 // float4 index within 32-node tile
        int n   = n0 + n4 * 4;
        float* dst = &s_pos[c * 33 + n4 * 4];
        if (n + 3 < N) {
            float4 v = *reinterpret_cast<const float4*>(pos + (size_t)c * N + n);
            dst[0] = v.x; dst[1] = v.y; dst[2] = v.z; dst[3] = v.w;
        } else {
            #pragma unroll
            for (int k = 0; k < 4; ++k) dst[k] = (n + k < N) ? pos[(size_t)c * N + n + k] : 0.f;
        }
    }
    #pragma unroll
    for (int it = 0; it < 2; ++it) {
        int idx = it * 256 + tid;
        int c   = idx >> 3;
        int n4  = idx & 7;
        int n   = n0 + n4 * 4;
        float* dst = &s_neg[c * 33 + n4 * 4];
        if (n + 3 < N) {
            float4 v = *reinterpret_cast<const float4*>(neg + (size_t)c * N + n);
            dst[0] = v.x; dst[1] = v.y; dst[2] = v.z; dst[3] = v.w;
        } else {
            #pragma unroll
            for (int k = 0; k < 4; ++k) dst[k] = (n + k < N) ? neg[(size_t)c * N + n + k] : 0.f;
        }
    }
    __syncthreads();

    // ---- Store phase (phi halves): 32 nodes x 16 uint4-chunks = 512 tasks ----
    #pragma unroll
    for (int it = 0; it < 2; ++it) {
        int idx  = it * 256 + tid;     // 0..511
        int nl   = idx >> 4;           // node-in-tile 0..31
        int u    = idx & 15;           // chunk 0..15  (0-7 pos, 8-15 neg)
        int node = n0 + nl;
        if (node >= N) continue;

        const float* s = (u < 8) ? s_pos : s_neg;
        int c0 = (u & 7) * 8;

        float f0 = s[(c0 + 0) * 33 + nl];
        float f1 = s[(c0 + 1) * 33 + nl];
        float f2 = s[(c0 + 2) * 33 + nl];
        float f3 = s[(c0 + 3) * 33 + nl];
        float f4 = s[(c0 + 4) * 33 + nl];
        float f5 = s[(c0 + 5) * 33 + nl];
        float f6 = s[(c0 + 6) * 33 + nl];
        float f7 = s[(c0 + 7) * 33 + nl];

        __half2 h0 = __floats2half2_rn(f0, f1);
        __half2 h1 = __floats2half2_rn(f2, f3);
        __half2 h2 = __floats2half2_rn(f4, f5);
        __half2 h3 = __floats2half2_rn(f6, f7);

        uint4 w;
        w.x = *reinterpret_cast<uint32_t*>(&h0);
        w.y = *reinterpret_cast<uint32_t*>(&h1);
        w.z = *reinterpret_cast<uint32_t*>(&h2);
        w.w = *reinterpret_cast<uint32_t*>(&h3);

        int foff = (u < 8) ? (u * 4) : (32 + (u - 8) * 4);   // float offset in row
        *reinterpret_cast<uint4*>(scratch + (size_t)node * ROW_F + foff) = w;
    }

    // ---- Inv-deg phase: 32 nodes x 4 float4 = 128 tasks ----
    if (tid < 128) {
        int nl   = tid >> 2;
        int q    = tid & 3;            // 0,1: pos halves; 2,3: neg halves
        int node = n0 + nl;
        if (node < N) {
            const float* dsrc = (q < 2) ? deg_pos : deg_neg;
            float4 d = *reinterpret_cast<const float4*>(dsrc + (size_t)node * 8 + (q & 1) * 4);
            float4 r;
            r.x = 1.0f / fmaxf(d.x, 1.0f);
            r.y = 1.0f / fmaxf(d.y, 1.0f);
            r.z = 1.0f / fmaxf(d.z, 1.0f);
            r.w = 1.0f / fmaxf(d.w, 1.0f);
            *reinterpret_cast<float4*>(scratch + (size_t)node * ROW_F + 64 + q * 4) = r;
        }
    }
}

// ---------------------------------------------------------------------------
// Kernel 2: one thread per (query, head).
// ---------------------------------------------------------------------------
__global__ __launch_bounds__(256) void iskde_gather_kernel(
    const float* __restrict__ q_phi,    // [Nq, 64]
    const float* __restrict__ scratch,  // [N, ROW_F] packed
    const int*   __restrict__ k_idx,    // [Nq]
    float* __restrict__ out,            // [2 * Nq * 8]
    int nq)
{
    int t = blockIdx.x * blockDim.x + threadIdx.x;
    int total = nq * 8;
    if (t >= total) return;

    int i = t >> 3;
    int h = t & 7;
    int j = __ldg(&k_idx[i]);

    const float4* qp = reinterpret_cast<const float4*>(q_phi + (size_t)t * 8);
    float4 q0 = qp[0];
    float4 q1 = qp[1];

    const float* row = scratch + (size_t)j * ROW_F;
    uint4 pw = *reinterpret_cast<const uint4*>(row + h * 4);        // 8 pos halves
    uint4 nw = *reinterpret_cast<const uint4*>(row + 32 + h * 4);   // 8 neg halves
    float invp = __ldg(row + 64 + h);
    float invn = __ldg(row + 72 + h);

    float2 p0 = __half22float2(*reinterpret_cast<__half2*>(&pw.x));
    float2 p1 = __half22float2(*reinterpret_cast<__half2*>(&pw.y));
    float2 p2 = __half22float2(*reinterpret_cast<__half2*>(&pw.z));
    float2 p3 = __half22float2(*reinterpret_cast<__half2*>(&pw.w));
    float2 m0 = __half22float2(*reinterpret_cast<__half2*>(&nw.x));
    float2 m1 = __half22float2(*reinterpret_cast<__half2*>(&nw.y));
    float2 m2 = __half22float2(*reinterpret_cast<__half2*>(&nw.z));
    float2 m3 = __half22float2(*reinterpret_cast<__half2*>(&nw.w));

    float dp = q0.x * p0.x + q0.y * p0.y + q0.z * p1.x + q0.w * p1.y
             + q1.x * p2.x + q1.y * p2.y + q1.z * p3.x + q1.w * p3.y;
    float dn = q0.x * m0.x + q0.y * m0.y + q0.z * m1.x + q0.w * m1.y
             + q1.x * m2.x + q1.y * m2.y + q1.z * m3.x + q1.w * m3.y;

    out[t]                 = dp * invp;
    out[(size_t)total + t] = dn * invn;
}

// ---------------------------------------------------------------------------
extern "C" void kernel_launch(void* const* d_in, const int* in_sizes, int n_in,
                              void* d_out, int out_size)
{
    const float* q_phi   = (const float*)d_in[0];
    const float* phi_pos = (const float*)d_in[1];
    const float* phi_neg = (const float*)d_in[2];
    const float* deg_pos = (const float*)d_in[3];
    const float* deg_neg = (const float*)d_in[4];
    const int*   k_idx   = (const int*)d_in[5];

    int nq = in_sizes[0] / 64;
    int N  = in_sizes[1] / 64;
    if (N > MAX_NODES) N = MAX_NODES;

    float* scratch;
    cudaGetSymbolAddress((void**)&scratch, g_scratch);

    int tblocks = (N + 31) / 32;
    pack_kernel<<<tblocks, 256>>>(phi_pos, phi_neg, deg_pos, deg_neg, scratch, N);

    int total   = nq * 8;
    int gblocks = (total + 255) / 256;
    iskde_gather_kernel<<<gblocks, 256>>>(q_phi, scratch, k_idx, (float*)d_out, nq);
}

// round 5
// speedup vs baseline: 1.3150x; 1.0101x over previous
#include <cuda_runtime.h>
#include <cuda_fp16.h>
#include <stdint.h>

#define MAX_N  500000
#define MAX_NQ 500000
#define TILE   128          // nodes per main-kernel block
#define ROW_H  132          // halves per smem row (128 + pad4): STS.64-aligned, <=2-way LDS banks
#define CHUNK  2048         // scan chunk (512 thr x 4)

__device__ unsigned g_counts[MAX_N];
__device__ unsigned g_cursor[MAX_N];
__device__ unsigned g_excl[MAX_N + 1];
__device__ unsigned g_bsums[256];
__device__ int g_sorted_i[MAX_NQ];
__device__ int g_sorted_j[MAX_NQ];

// ---- K0: zero counts + cursor ----
__global__ void zero_k(int N) {
    int i = blockIdx.x * blockDim.x + threadIdx.x;
    if (i < N) { g_counts[i] = 0u; g_cursor[i] = 0u; }
}

// ---- K1: histogram of k_indices ----
__global__ void hist_k(const int* __restrict__ k_idx, int nq) {
    int i = blockIdx.x * blockDim.x + threadIdx.x;
    if (i < nq) atomicAdd(&g_counts[k_idx[i]], 1u);
}

// ---- S1: per-chunk exclusive scan (chunk = 2048 = 512 thr x 4) ----
__global__ __launch_bounds__(512) void scan1_k(int N) {
    __shared__ unsigned s[512];
    int tid  = threadIdx.x;
    int base = blockIdx.x * CHUNK;
    int i0   = base + tid * 4;
    unsigned v0 = (i0 + 0 < N) ? g_counts[i0 + 0] : 0u;
    unsigned v1 = (i0 + 1 < N) ? g_counts[i0 + 1] : 0u;
    unsigned v2 = (i0 + 2 < N) ? g_counts[i0 + 2] : 0u;
    unsigned v3 = (i0 + 3 < N) ? g_counts[i0 + 3] : 0u;
    unsigned mysum = v0 + v1 + v2 + v3;
    s[tid] = mysum;
    __syncthreads();
    for (int off = 1; off < 512; off <<= 1) {
        unsigned t = (tid >= off) ? s[tid - off] : 0u;
        __syncthreads();
        if (tid >= off) s[tid] += t;
        __syncthreads();
    }
    unsigned run = s[tid] - mysum;   // exclusive prefix of this thread's group
    if (i0 + 0 < N) g_excl[i0 + 0] = run;            run += v0;
    if (i0 + 1 < N) g_excl[i0 + 1] = run;            run += v1;
    if (i0 + 2 < N) g_excl[i0 + 2] = run;            run += v2;
    if (i0 + 3 < N) g_excl[i0 + 3] = run;
    if (tid == 511) g_bsums[blockIdx.x] = s[511];
}

// ---- S2: scan the (<=256) chunk sums; write sentinel ----
__global__ __launch_bounds__(256) void scan2_k(int nchunks, int N, int nq) {
    __shared__ unsigned s[256];
    int tid = threadIdx.x;
    unsigned v = (tid < nchunks) ? g_bsums[tid] : 0u;
    s[tid] = v;
    __syncthreads();
    for (int off = 1; off < 256; off <<= 1) {
        unsigned t = (tid >= off) ? s[tid - off] : 0u;
        __syncthreads();
        if (tid >= off) s[tid] += t;
        __syncthreads();
    }
    if (tid < nchunks) g_bsums[tid] = s[tid] - v;    // exclusive
    if (tid == 0) g_excl[N] = (unsigned)nq;          // sentinel
}

// ---- S3: add chunk offsets ----
__global__ void scan3_k(int N) {
    int i = blockIdx.x * blockDim.x + threadIdx.x;
    if (i < N) g_excl[i] += g_bsums[i >> 11];
}

// ---- K3: scatter queries into node-sorted order ----
__global__ void perm_k(const int* __restrict__ k_idx, int nq) {
    int i = blockIdx.x * blockDim.x + threadIdx.x;
    if (i < nq) {
        int j = k_idx[i];
        unsigned pos = g_excl[j] + atomicAdd(&g_cursor[j], 1u);
        g_sorted_i[pos] = i;
        g_sorted_j[pos] = j;
    }
}

// ---- K4: main fused kernel ----
// Block owns nodes [n0, n0+TILE). Phase 1: coalesced-load phi slice (both signs)
// into channel-major fp16 smem. Phase 2: serve this range's sorted queries.
__global__ __launch_bounds__(256) void main_k(
    const float* __restrict__ q_phi,     // [nq, 64]
    const float* __restrict__ pos,       // [64, N]
    const float* __restrict__ neg,       // [64, N]
    const float* __restrict__ deg_pos,   // [N, 8]
    const float* __restrict__ deg_neg,   // [N, 8]
    float* __restrict__ out,             // [2*nq*8]
    int N, int nq)
{
    __shared__ __half sh[128 * ROW_H];   // rows: ch 0..63 = pos, 64..127 = neg
    const int n0  = blockIdx.x * TILE;
    const int tid = threadIdx.x;

    // Phase 1: 128 rows x 32 float4 = 4096 tasks, 16 iters of 256 threads.
    // Warp covers one row (32 float4 = 512 B contiguous) -> fully coalesced.
    #pragma unroll
    for (int it = 0; it < 16; ++it) {
        int idx = it * 256 + tid;
        int c   = idx >> 5;           // packed channel 0..127
        int n4  = idx & 31;
        int n   = n0 + n4 * 4;
        const float* src = (c < 64) ? (pos + (size_t)c * N)
                                    : (neg + (size_t)(c - 64) * N);
        float x0 = 0.f, x1 = 0.f, x2 = 0.f, x3 = 0.f;
        if (n + 3 < N) {
            float4 v = *reinterpret_cast<const float4*>(src + n);
            x0 = v.x; x1 = v.y; x2 = v.z; x3 = v.w;
        } else if (n < N) {
            x0 = src[n];
            if (n + 1 < N) x1 = src[n + 1];
            if (n + 2 < N) x2 = src[n + 2];
        }
        __half2* d = reinterpret_cast<__half2*>(&sh[c * ROW_H + n4 * 4]);
        d[0] = __floats2half2_rn(x0, x1);
        d[1] = __floats2half2_rn(x2, x3);
    }
    __syncthreads();

    // Phase 2: tasks = (query, head). 8 consecutive tasks = one query.
    const unsigned qlo = g_excl[n0];
    const unsigned qhi = g_excl[(n0 + TILE < N) ? (n0 + TILE) : N];
    const size_t total = (size_t)nq * 8;

    for (unsigned s8 = qlo * 8u + tid; s8 < qhi * 8u; s8 += 256u) {
        unsigned s = s8 >> 3;
        int h = (int)(s8 & 7u);
        int i = g_sorted_i[s];
        int j = g_sorted_j[s];
        int nl = j - n0;

        const float4* qp = reinterpret_cast<const float4*>(q_phi + (size_t)i * 64 + h * 8);
        float4 q0 = qp[0];
        float4 q1 = qp[1];
        float qv[8] = {q0.x, q0.y, q0.z, q0.w, q1.x, q1.y, q1.z, q1.w};

        int cb = h * 8;
        float dp = 0.f, dn = 0.f;
        #pragma unroll
        for (int kk = 0; kk < 8; ++kk) {
            float pv = __half2float(sh[(cb + kk) * ROW_H + nl]);
            float nv = __half2float(sh[(64 + cb + kk) * ROW_H + nl]);
            dp += qv[kk] * pv;
            dn += qv[kk] * nv;
        }

        float denp = fmaxf(__ldg(deg_pos + (size_t)j * 8 + h), 1.0f);
        float denn = fmaxf(__ldg(deg_neg + (size_t)j * 8 + h), 1.0f);

        out[(size_t)i * 8 + h]         = dp / denp;
        out[total + (size_t)i * 8 + h] = dn / denn;
    }
}

// ---------------------------------------------------------------------------
extern "C" void kernel_launch(void* const* d_in, const int* in_sizes, int n_in,
                              void* d_out, int out_size)
{
    const float* q_phi   = (const float*)d_in[0];
    const float* phi_pos = (const float*)d_in[1];
    const float* phi_neg = (const float*)d_in[2];
    const float* deg_pos = (const float*)d_in[3];
    const float* deg_neg = (const float*)d_in[4];
    const int*   k_idx   = (const int*)d_in[5];

    int nq = in_sizes[0] / 64;
    int N  = in_sizes[1] / 64;
    if (N  > MAX_N)  N  = MAX_N;
    if (nq > MAX_NQ) nq = MAX_NQ;

    int nchunks = (N + CHUNK - 1) / CHUNK;      // 245 for N=500k (<=256)

    zero_k <<<(N  + 255) / 256, 256>>>(N);
    hist_k <<<(nq + 255) / 256, 256>>>(k_idx, nq);
    scan1_k<<<nchunks, 512>>>(N);
    scan2_k<<<1, 256>>>(nchunks, N, nq);
    scan3_k<<<(N  + 255) / 256, 256>>>(N);
    perm_k <<<(nq + 255) / 256, 256>>>(k_idx, nq);

    int mblocks = (N + TILE - 1) / TILE;
    main_k <<<mblocks, 256>>>(q_phi, phi_pos, phi_neg, deg_pos, deg_neg,
                              (float*)d_out, N, nq);
}

// round 8
// speedup vs baseline: 1.6662x; 1.2670x over previous
#include <cuda_runtime.h>
#include <cuda_fp16.h>
#include <stdint.h>

#define MAX_N  500000
#define MAX_NQ 500000
#define TILE   128           // nodes per main-kernel block (power of 2: nl = j & 127)
#define ROWB   272           // smem bytes per node row: 256 data + 16 pad (bank step 68%32=4)
#define CHUNK  2048          // scan chunk (512 thr x 4)

__device__ unsigned g_counts[MAX_N];
__device__ unsigned g_excl[MAX_N];
__device__ unsigned g_bsums[256];
__device__ unsigned g_sorted[MAX_NQ];   // (query_i << 7) | (node & 127)

// ---- K0: zero counts ----
__global__ void zero_k(int N) {
    int i = blockIdx.x * blockDim.x + threadIdx.x;
    if (i < N) g_counts[i] = 0u;
}

// ---- K1: histogram of k_indices ----
__global__ void hist_k(const int* __restrict__ k_idx, int nq) {
    int i = blockIdx.x * blockDim.x + threadIdx.x;
    if (i < nq) atomicAdd(&g_counts[k_idx[i]], 1u);
}

// ---- S1: per-chunk exclusive scan (chunk = 2048 = 512 thr x 4) ----
__global__ __launch_bounds__(512) void scan1_k(int N) {
    __shared__ unsigned s[512];
    int tid  = threadIdx.x;
    int i0   = blockIdx.x * CHUNK + tid * 4;
    unsigned v0 = (i0 + 0 < N) ? g_counts[i0 + 0] : 0u;
    unsigned v1 = (i0 + 1 < N) ? g_counts[i0 + 1] : 0u;
    unsigned v2 = (i0 + 2 < N) ? g_counts[i0 + 2] : 0u;
    unsigned v3 = (i0 + 3 < N) ? g_counts[i0 + 3] : 0u;
    unsigned mysum = v0 + v1 + v2 + v3;
    s[tid] = mysum;
    __syncthreads();
    for (int off = 1; off < 512; off <<= 1) {
        unsigned t = (tid >= off) ? s[tid - off] : 0u;
        __syncthreads();
        if (tid >= off) s[tid] += t;
        __syncthreads();
    }
    unsigned run = s[tid] - mysum;
    if (i0 + 0 < N) g_excl[i0 + 0] = run;  run += v0;
    if (i0 + 1 < N) g_excl[i0 + 1] = run;  run += v1;
    if (i0 + 2 < N) g_excl[i0 + 2] = run;  run += v2;
    if (i0 + 3 < N) g_excl[i0 + 3] = run;
    if (tid == 511) g_bsums[blockIdx.x] = s[511];
}

// ---- S2: each block redundantly scans the (<=256) chunk sums, adds offset ----
__global__ __launch_bounds__(256) void scan2_k(int nchunks, int N) {
    __shared__ unsigned s[256];
    __shared__ unsigned e[256];
    int tid = threadIdx.x;
    unsigned v = (tid < nchunks) ? g_bsums[tid] : 0u;
    s[tid] = v;
    __syncthreads();
    for (int off = 1; off < 256; off <<= 1) {
        unsigned t = (tid >= off) ? s[tid - off] : 0u;
        __syncthreads();
        if (tid >= off) s[tid] += t;
        __syncthreads();
    }
    e[tid] = s[tid] - v;     // exclusive chunk prefix
    __syncthreads();
    int i = blockIdx.x * 256 + tid;
    if (i < N) g_excl[i] += e[i >> 11];
}

// ---- K3: scatter queries into node-sorted order (bumps g_excl in place) ----
// After this kernel: g_excl[j] == excl_orig[j+1] for every j (counts included).
__global__ void perm_k(const int* __restrict__ k_idx, int nq) {
    int i = blockIdx.x * blockDim.x + threadIdx.x;
    if (i < nq) {
        int j = k_idx[i];
        unsigned pos = atomicAdd(&g_excl[j], 1u);
        g_sorted[pos] = ((unsigned)i << 7) | (unsigned)(j & (TILE - 1));
    }
}

// ---- K4: main fused kernel ----
__global__ __launch_bounds__(256) void main_k(
    const float* __restrict__ q_phi,     // [nq, 64]
    const float* __restrict__ pos,       // [64, N]
    const float* __restrict__ neg,       // [64, N]
    const float* __restrict__ deg_pos,   // [N, 8]
    const float* __restrict__ deg_neg,   // [N, 8]
    float* __restrict__ out,             // [2*nq*8]
    int N, int nq)
{
    __shared__ __align__(16) char sh[TILE * ROWB];   // node-major fp16, 34.0 KB
    const int n0  = blockIdx.x * TILE;
    const int tid = threadIdx.x;

    // ---- Phase 1: load phi slice, store node-major fp16 ----
    // Task = (group g 0..15, node nl 0..127). g<8: pos channels g*8..g*8+7, g>=8: neg.
    // Warp: fixed (g, nl32), lanes = 32 consecutive nodes -> gmem coalesced 128B/iter;
    // STS.128 with 272B row pitch -> conflict-free.
    #pragma unroll
    for (int it = 0; it < 8; ++it) {
        int idx  = it * 256 + tid;           // 0..2047
        int lane = idx & 31;
        int nl32 = (idx >> 5) & 3;
        int g    = idx >> 7;                 // 0..15
        int nl   = nl32 * 32 + lane;
        int n    = n0 + nl;
        const float* src = (g < 8) ? (pos + (size_t)(g * 8) * N)
                                   : (neg + (size_t)((g - 8) * 8) * N);
        float f[8];
        #pragma unroll
        for (int kk = 0; kk < 8; ++kk)
            f[kk] = (n < N) ? src[(size_t)kk * N + n] : 0.f;

        __half2 h0 = __floats2half2_rn(f[0], f[1]);
        __half2 h1 = __floats2half2_rn(f[2], f[3]);
        __half2 h2 = __floats2half2_rn(f[4], f[5]);
        __half2 h3 = __floats2half2_rn(f[6], f[7]);
        uint4 w;
        w.x = *reinterpret_cast<uint32_t*>(&h0);
        w.y = *reinterpret_cast<uint32_t*>(&h1);
        w.z = *reinterpret_cast<uint32_t*>(&h2);
        w.w = *reinterpret_cast<uint32_t*>(&h3);
        *reinterpret_cast<uint4*>(sh + nl * ROWB + g * 16) = w;
    }
    __syncthreads();

    // ---- Phase 2: serve sorted queries for node range [n0, n0+TILE) ----
    int hiIdx = n0 + TILE - 1; if (hiIdx > N - 1) hiIdx = N - 1;
    const unsigned qlo = (n0 == 0) ? 0u : g_excl[n0 - 1];   // == excl_orig[n0]
    const unsigned qhi = g_excl[hiIdx];                     // == excl_orig[n0+TILE] (or nq)
    const size_t total = (size_t)nq * 8;

    for (unsigned s8 = qlo * 8u + tid; s8 < qhi * 8u; s8 += 256u) {
        unsigned srec = g_sorted[s8 >> 3];
        int h  = (int)(s8 & 7u);
        int i  = (int)(srec >> 7);
        int nl = (int)(srec & (TILE - 1));
        int j  = n0 + nl;

        const float4* qp = reinterpret_cast<const float4*>(q_phi + (size_t)i * 64 + h * 8);
        float4 q0 = qp[0];
        float4 q1 = qp[1];

        uint4 pw = *reinterpret_cast<const uint4*>(sh + nl * ROWB + h * 16);
        uint4 nw = *reinterpret_cast<const uint4*>(sh + nl * ROWB + 128 + h * 16);

        float2 p0 = __half22float2(*reinterpret_cast<__half2*>(&pw.x));
        float2 p1 = __half22float2(*reinterpret_cast<__half2*>(&pw.y));
        float2 p2 = __half22float2(*reinterpret_cast<__half2*>(&pw.z));
        float2 p3 = __half22float2(*reinterpret_cast<__half2*>(&pw.w));
        float2 m0 = __half22float2(*reinterpret_cast<__half2*>(&nw.x));
        float2 m1 = __half22float2(*reinterpret_cast<__half2*>(&nw.y));
        float2 m2 = __half22float2(*reinterpret_cast<__half2*>(&nw.z));
        float2 m3 = __half22float2(*reinterpret_cast<__half2*>(&nw.w));

        float dp = q0.x * p0.x + q0.y * p0.y + q0.z * p1.x + q0.w * p1.y
                 + q1.x * p2.x + q1.y * p2.y + q1.z * p3.x + q1.w * p3.y;
        float dn = q0.x * m0.x + q0.y * m0.y + q0.z * m1.x + q0.w * m1.y
                 + q1.x * m2.x + q1.y * m2.y + q1.z * m3.x + q1.w * m3.y;

        float denp = fmaxf(__ldg(deg_pos + (size_t)j * 8 + h), 1.0f);
        float denn = fmaxf(__ldg(deg_neg + (size_t)j * 8 + h), 1.0f);

        out[(size_t)i * 8 + h]         = dp / denp;
        out[total + (size_t)i * 8 + h] = dn / denn;
    }
}

// ---------------------------------------------------------------------------
extern "C" void kernel_launch(void* const* d_in, const int* in_sizes, int n_in,
                              void* d_out, int out_size)
{
    const float* q_phi   = (const float*)d_in[0];
    const float* phi_pos = (const float*)d_in[1];
    const float* phi_neg = (const float*)d_in[2];
    const float* deg_pos = (const float*)d_in[3];
    const float* deg_neg = (const float*)d_in[4];
    const int*   k_idx   = (const int*)d_in[5];

    int nq = in_sizes[0] / 64;
    int N  = in_sizes[1] / 64;
    if (N  > MAX_N)  N  = MAX_N;
    if (nq > MAX_NQ) nq = MAX_NQ;

    int nchunks = (N + CHUNK - 1) / CHUNK;      // 245 for N=500k (<=256)

    zero_k <<<(N  + 255) / 256, 256>>>(N);
    hist_k <<<(nq + 255) / 256, 256>>>(k_idx, nq);
    scan1_k<<<nchunks, 512>>>(N);
    scan2_k<<<(N + 255) / 256, 256>>>(nchunks, N);
    perm_k <<<(nq + 255) / 256, 256>>>(k_idx, nq);

    int mblocks = (N + TILE - 1) / TILE;
    main_k <<<mblocks, 256>>>(q_phi, phi_pos, phi_neg, deg_pos, deg_neg,
                              (float*)d_out, N, nq);
}

// round 10
// speedup vs baseline: 1.7264x; 1.0362x over previous
#include <cuda_runtime.h>
#include <cuda_fp16.h>
#include <stdint.h>

#define MAX_N  500000
#define MAX_NQ 500000
#define TILE   128           // nodes per main-kernel block (power of 2: nl = j & 127)
#define ROWB   272           // smem bytes per node row: 256 data + 16 pad (bank step 68%32=4)
#define CHUNK  2048          // scan chunk (512 thr x 4); TILE divides CHUNK

__device__ unsigned g_counts[MAX_N];      // zero-initialized at load; re-zeroed by main_k
__device__ unsigned g_excl[MAX_N];        // per-chunk local exclusive prefix (bumped by perm)
__device__ unsigned g_bsums[256];         // per-chunk totals
__device__ unsigned g_cexcl[257];         // exclusive scan of chunk totals (+ total at end)
__device__ unsigned g_sorted[MAX_NQ];     // (query_i << 7) | (node & 127)

// ---- K1: histogram of k_indices (counts pre-zeroed by previous main_k) ----
__global__ void hist_k(const int* __restrict__ k_idx, int nq) {
    int i = blockIdx.x * blockDim.x + threadIdx.x;
    if (i < nq) atomicAdd(&g_counts[k_idx[i]], 1u);
}

// ---- S1: per-chunk local exclusive scan (chunk = 2048 = 512 thr x 4) ----
__global__ __launch_bounds__(512) void scan1_k(int N) {
    __shared__ unsigned s[512];
    int tid  = threadIdx.x;
    int i0   = blockIdx.x * CHUNK + tid * 4;
    unsigned v0 = (i0 + 0 < N) ? g_counts[i0 + 0] : 0u;
    unsigned v1 = (i0 + 1 < N) ? g_counts[i0 + 1] : 0u;
    unsigned v2 = (i0 + 2 < N) ? g_counts[i0 + 2] : 0u;
    unsigned v3 = (i0 + 3 < N) ? g_counts[i0 + 3] : 0u;
    unsigned mysum = v0 + v1 + v2 + v3;
    s[tid] = mysum;
    __syncthreads();
    for (int off = 1; off < 512; off <<= 1) {
        unsigned t = (tid >= off) ? s[tid - off] : 0u;
        __syncthreads();
        if (tid >= off) s[tid] += t;
        __syncthreads();
    }
    unsigned run = s[tid] - mysum;   // local (within-chunk) exclusive prefix
    if (i0 + 0 < N) g_excl[i0 + 0] = run;  run += v0;
    if (i0 + 1 < N) g_excl[i0 + 1] = run;  run += v1;
    if (i0 + 2 < N) g_excl[i0 + 2] = run;  run += v2;
    if (i0 + 3 < N) g_excl[i0 + 3] = run;
    if (tid == 511) g_bsums[blockIdx.x] = s[511];
}

// ---- SB: single block scans the (<=256) chunk sums -> g_cexcl ----
__global__ __launch_bounds__(256) void scanb_k(int nchunks, int nq) {
    __shared__ unsigned s[256];
    int tid = threadIdx.x;
    unsigned v = (tid < nchunks) ? g_bsums[tid] : 0u;
    s[tid] = v;
    __syncthreads();
    for (int off = 1; off < 256; off <<= 1) {
        unsigned t = (tid >= off) ? s[tid - off] : 0u;
        __syncthreads();
        if (tid >= off) s[tid] += t;
        __syncthreads();
    }
    if (tid < nchunks) g_cexcl[tid] = s[tid] - v;   // exclusive
    if (tid == 0) g_cexcl[nchunks] = (unsigned)nq;  // total
}

// ---- K3: scatter queries into node-sorted order ----
// Post-condition: g_excl[j] == local inclusive prefix at j (local excl + count).
__global__ void perm_k(const int* __restrict__ k_idx, int nq) {
    int i = blockIdx.x * blockDim.x + threadIdx.x;
    if (i < nq) {
        int j = k_idx[i];
        unsigned pos = g_cexcl[j >> 11] + atomicAdd(&g_excl[j], 1u);
        g_sorted[pos] = ((unsigned)i << 7) | (unsigned)(j & (TILE - 1));
    }
}

// ---- K4: main fused kernel ----
__global__ __launch_bounds__(256) void main_k(
    const float* __restrict__ q_phi,     // [nq, 64]
    const float* __restrict__ pos,       // [64, N]
    const float* __restrict__ neg,       // [64, N]
    const float* __restrict__ deg_pos,   // [N, 8]
    const float* __restrict__ deg_neg,   // [N, 8]
    float* __restrict__ out,             // [2*nq*8]
    int N, int nq)
{
    __shared__ __align__(16) char sh[TILE * ROWB];   // node-major fp16, 34.0 KB
    const int n0  = blockIdx.x * TILE;
    const int tid = threadIdx.x;

    // ---- Phase 1: load phi slice, store node-major fp16 ----
    // Task = (group g 0..15, node nl 0..127). g<8: pos channels g*8..g*8+7, g>=8: neg.
    #pragma unroll
    for (int it = 0; it < 8; ++it) {
        int idx  = it * 256 + tid;           // 0..2047
        int lane = idx & 31;
        int nl32 = (idx >> 5) & 3;
        int g    = idx >> 7;                 // 0..15
        int nl   = nl32 * 32 + lane;
        int n    = n0 + nl;
        const float* src = (g < 8) ? (pos + (size_t)(g * 8) * N)
                                   : (neg + (size_t)((g - 8) * 8) * N);
        float f[8];
        #pragma unroll
        for (int kk = 0; kk < 8; ++kk)
            f[kk] = (n < N) ? src[(size_t)kk * N + n] : 0.f;

        __half2 h0 = __floats2half2_rn(f[0], f[1]);
        __half2 h1 = __floats2half2_rn(f[2], f[3]);
        __half2 h2 = __floats2half2_rn(f[4], f[5]);
        __half2 h3 = __floats2half2_rn(f[6], f[7]);
        uint4 w;
        w.x = *reinterpret_cast<uint32_t*>(&h0);
        w.y = *reinterpret_cast<uint32_t*>(&h1);
        w.z = *reinterpret_cast<uint32_t*>(&h2);
        w.w = *reinterpret_cast<uint32_t*>(&h3);
        *reinterpret_cast<uint4*>(sh + nl * ROWB + g * 16) = w;
    }
    __syncthreads();

    // ---- Phase 2: serve sorted queries for node range [n0, n0+TILE) ----
    // Global excl at n0:    g_cexcl[n0>>11] + (n0 at chunk start ? 0 : g_excl[n0-1])
    // Global excl at n0+T:  nq if beyond N; g_cexcl[e>>11] if e at chunk start;
    //                       else g_cexcl[e>>11] + g_excl[e-1].
    unsigned qlo = g_cexcl[n0 >> 11];
    if (n0 & (CHUNK - 1)) qlo += g_excl[n0 - 1];
    int e = n0 + TILE;
    unsigned qhi;
    if (e >= N)                 qhi = (unsigned)nq;
    else if ((e & (CHUNK - 1)) == 0) qhi = g_cexcl[e >> 11];
    else                        qhi = g_cexcl[e >> 11] + g_excl[e - 1];

    const size_t total = (size_t)nq * 8;

    for (unsigned s8 = qlo * 8u + tid; s8 < qhi * 8u; s8 += 256u) {
        unsigned srec = g_sorted[s8 >> 3];
        int h  = (int)(s8 & 7u);
        int i  = (int)(srec >> 7);
        int nl = (int)(srec & (TILE - 1));
        int j  = n0 + nl;

        const float4* qp = reinterpret_cast<const float4*>(q_phi + (size_t)i * 64 + h * 8);
        float4 q0 = qp[0];
        float4 q1 = qp[1];

        uint4 pw = *reinterpret_cast<const uint4*>(sh + nl * ROWB + h * 16);
        uint4 nw = *reinterpret_cast<const uint4*>(sh + nl * ROWB + 128 + h * 16);

        float2 p0 = __half22float2(*reinterpret_cast<__half2*>(&pw.x));
        float2 p1 = __half22float2(*reinterpret_cast<__half2*>(&pw.y));
        float2 p2 = __half22float2(*reinterpret_cast<__half2*>(&pw.z));
        float2 p3 = __half22float2(*reinterpret_cast<__half2*>(&pw.w));
        float2 m0 = __half22float2(*reinterpret_cast<__half2*>(&nw.x));
        float2 m1 = __half22float2(*reinterpret_cast<__half2*>(&nw.y));
        float2 m2 = __half22float2(*reinterpret_cast<__half2*>(&nw.z));
        float2 m3 = __half22float2(*reinterpret_cast<__half2*>(&nw.w));

        float dp = q0.x * p0.x + q0.y * p0.y + q0.z * p1.x + q0.w * p1.y
                 + q1.x * p2.x + q1.y * p2.y + q1.z * p3.x + q1.w * p3.y;
        float dn = q0.x * m0.x + q0.y * m0.y + q0.z * m1.x + q0.w * m1.y
                 + q1.x * m2.x + q1.y * m2.y + q1.z * m3.x + q1.w * m3.y;

        float denp = fmaxf(__ldg(deg_pos + (size_t)j * 8 + h), 1.0f);
        float denn = fmaxf(__ldg(deg_neg + (size_t)j * 8 + h), 1.0f);

        out[(size_t)i * 8 + h]         = dp / denp;
        out[total + (size_t)i * 8 + h] = dn / denn;
    }

    // ---- Phase 3: re-zero this tile's counts for the next replay ----
    if (tid < TILE) {
        int n = n0 + tid;
        if (n < N) g_counts[n] = 0u;
    }
}

// ---------------------------------------------------------------------------
extern "C" void kernel_launch(void* const* d_in, const int* in_sizes, int n_in,
                              void* d_out, int out_size)
{
    const float* q_phi   = (const float*)d_in[0];
    const float* phi_pos = (const float*)d_in[1];
    const float* phi_neg = (const float*)d_in[2];
    const float* deg_pos = (const float*)d_in[3];
    const float* deg_neg = (const float*)d_in[4];
    const int*   k_idx   = (const int*)d_in[5];

    int nq = in_sizes[0] / 64;
    int N  = in_sizes[1] / 64;
    if (N  > MAX_N)  N  = MAX_N;
    if (nq > MAX_NQ) nq = MAX_NQ;

    int nchunks = (N + CHUNK - 1) / CHUNK;      // 245 for N=500k (<=256)

    hist_k <<<(nq + 255) / 256, 256>>>(k_idx, nq);
    scan1_k<<<nchunks, 512>>>(N);
    scanb_k<<<1, 256>>>(nchunks, nq);
    perm_k <<<(nq + 255) / 256, 256>>>(k_idx, nq);

    int mblocks = (N + TILE - 1) / TILE;
    main_k <<<mblocks, 256>>>(q_phi, phi_pos, phi_neg, deg_pos, deg_neg,
                              (float*)d_out, N, nq);
}